// round 1
// baseline (speedup 1.0000x reference)
#include <cuda_runtime.h>
#include <math.h>

// Problem constants
#define NROWS 32768   // B*H*W
#define CDIM  128
#define KCODES 8192
#define BB 32
#define HH 32
#define WW 32

// Output buffer layout: [loss(1)] [out(B*C*H*W)] [perplexity(1)] [idx(NROWS)]
#define OUT_OFF  1
#define PERP_OFF (1 + NROWS*CDIM)
#define IDX_OFF  (PERP_OFF + 1)

// Scratch (static __device__ — no allocations allowed)
__device__ float g_z[NROWS*CDIM];      // projected inputs [N,C]
__device__ float g_zsq[NROWS];         // row squared norms of z
__device__ float g_esq[KCODES];        // row squared norms of emb
__device__ float g_wt[CDIM*CDIM];      // W_lin transposed: g_wt[c*C + j] = W[j,c]
__device__ int   g_idx[NROWS];         // argmin indices
__device__ float g_part[1024];         // per-block SSE partials
__device__ unsigned int g_hist[KCODES];// code usage histogram

// ---------------------------------------------------------------------------
// Prep: transpose W into g_wt, zero histogram
__global__ void k_prep(const float* __restrict__ Wl) {
    int i = blockIdx.x * 256 + threadIdx.x;
    if (i < CDIM*CDIM) {
        int j = i / CDIM, c = i % CDIM;
        g_wt[c*CDIM + j] = Wl[i];
    }
    int h = i - CDIM*CDIM;
    if (h >= 0 && h < KCODES) g_hist[h] = 0u;
}

// Row squared norms of emb: warp per row
__global__ void k_esq(const float* __restrict__ emb) {
    int warp = (blockIdx.x * blockDim.x + threadIdx.x) >> 5;
    int lane = threadIdx.x & 31;
    if (warp >= KCODES) return;
    const float* p = emb + (size_t)warp * CDIM;
    float s = 0.f;
    #pragma unroll
    for (int c = lane; c < CDIM; c += 32) { float v = p[c]; s += v*v; }
    #pragma unroll
    for (int o = 16; o > 0; o >>= 1) s += __shfl_xor_sync(0xffffffffu, s, o);
    if (lane == 0) g_esq[warp] = s;
}

// Row squared norms of z: warp per row
__global__ void k_zsq() {
    int warp = (blockIdx.x * blockDim.x + threadIdx.x) >> 5;
    int lane = threadIdx.x & 31;
    if (warp >= NROWS) return;
    const float* p = g_z + (size_t)warp * CDIM;
    float s = 0.f;
    #pragma unroll
    for (int c = lane; c < CDIM; c += 32) { float v = p[c]; s += v*v; }
    #pragma unroll
    for (int o = 16; o > 0; o >>= 1) s += __shfl_xor_sync(0xffffffffu, s, o);
    if (lane == 0) g_zsq[warp] = s;
}

// ---------------------------------------------------------------------------
// Linear projection: z[n,j] = sum_c x[b,c,h,w] * W[j,c] + b[j]
// Block per (b,h) strip (32 rows), 128 threads (one per output channel j).
__global__ void k_linear(const float* __restrict__ x, const float* __restrict__ bl) {
    __shared__ float xs[CDIM*WW];   // xs[c*32 + w]
    int bh = blockIdx.x;
    int b = bh >> 5, h = bh & 31;
    int tid = threadIdx.x;          // 128
    int w = tid & 31, cg = tid >> 5;
    const float* xp = x + ((size_t)(b*CDIM) * HH + h) * WW;  // x[b,0,h,0]
    #pragma unroll
    for (int cc = 0; cc < 32; cc++) {
        int c = cg*32 + cc;
        xs[c*WW + w] = xp[(size_t)c * (HH*WW) + w];
    }
    __syncthreads();

    int j = tid;
    float bj = bl[j];
    float acc[WW];
    #pragma unroll
    for (int ww = 0; ww < WW; ww++) acc[ww] = bj;

    #pragma unroll 4
    for (int c = 0; c < CDIM; c++) {
        float wv = g_wt[c*CDIM + j];
        #pragma unroll
        for (int w4 = 0; w4 < WW/4; w4++) {
            float4 xv = *(const float4*)&xs[c*WW + w4*4];
            acc[w4*4+0] += xv.x * wv;
            acc[w4*4+1] += xv.y * wv;
            acc[w4*4+2] += xv.z * wv;
            acc[w4*4+3] += xv.w * wv;
        }
    }
    int nbase = bh * WW;
    #pragma unroll
    for (int ww = 0; ww < WW; ww++)
        g_z[(size_t)(nbase+ww)*CDIM + j] = acc[ww];
}

// ---------------------------------------------------------------------------
// Fused distance + argmin. Block: 128 rows x (loop over K in 128-code tiles).
// 256 threads (16x16), 8x8 micro-tile per thread, packed f32x2 FMA.
#define RM 128
#define KN 128
#define SMEM_ARGMIN ((RM*CDIM + KN*CDIM + KN) * 4)

__global__ void __launch_bounds__(256, 1) k_argmin(const float* __restrict__ emb) {
    extern __shared__ float sm[];
    float* zs  = sm;                 // RM*CDIM
    float* es  = sm + RM*CDIM;       // KN*CDIM
    float* ssq = es + KN*CDIM;       // KN

    int tid = threadIdx.x;
    int tx = tid & 15, ty = tid >> 4;
    int rowbase = blockIdx.x * RM;

    // Load z tile (resident for whole K loop)
    {
        const float4* src = (const float4*)(g_z + (size_t)rowbase * CDIM);
        float4* dst = (float4*)zs;
        for (int i = tid; i < RM*CDIM/4; i += 256) dst[i] = src[i];
    }
    float zsqr[8];
    #pragma unroll
    for (int i = 0; i < 8; i++) zsqr[i] = g_zsq[rowbase + ty*8 + i];

    float bestv[8]; int besti[8];
    #pragma unroll
    for (int i = 0; i < 8; i++) { bestv[i] = 3.0e38f; besti[i] = 0; }

    const float* zp = zs + (ty*8) * CDIM;
    const float* ep = es + (tx*8) * CDIM;

    for (int kt = 0; kt < KCODES; kt += KN) {
        __syncthreads();   // previous tile fully consumed
        {
            const float4* src = (const float4*)(emb + (size_t)kt * CDIM);
            float4* dst = (float4*)es;
            for (int i = tid; i < KN*CDIM/4; i += 256) dst[i] = src[i];
            if (tid < KN) ssq[tid] = g_esq[kt + tid];
        }
        __syncthreads();

        unsigned long long acc[8][8];
        #pragma unroll
        for (int i = 0; i < 8; i++)
            #pragma unroll
            for (int j = 0; j < 8; j++) acc[i][j] = 0ull;

        #pragma unroll 2
        for (int c = 0; c < CDIM; c += 2) {
            unsigned long long af[8], bf[8];
            #pragma unroll
            for (int i = 0; i < 8; i++)
                af[i] = *(const unsigned long long*)(zp + i*CDIM + c);
            #pragma unroll
            for (int j = 0; j < 8; j++)
                bf[j] = *(const unsigned long long*)(ep + j*CDIM + c);
            #pragma unroll
            for (int i = 0; i < 8; i++)
                #pragma unroll
                for (int j = 0; j < 8; j++)
                    asm("fma.rn.f32x2 %0, %1, %2, %0;"
                        : "+l"(acc[i][j]) : "l"(af[i]), "l"(bf[j]));
        }

        // Epilogue: d = (zsq + esq) - 2*dot, rounding order matching reference.
        #pragma unroll
        for (int i = 0; i < 8; i++) {
            #pragma unroll
            for (int j = 0; j < 8; j++) {
                float lo = __uint_as_float((unsigned int)(acc[i][j] & 0xffffffffull));
                float hi = __uint_as_float((unsigned int)(acc[i][j] >> 32));
                float dot = __fadd_rn(lo, hi);
                float se  = __fadd_rn(zsqr[i], ssq[tx*8 + j]);
                float d   = __fsub_rn(se, __fmul_rn(2.0f, dot));
                if (d < bestv[i]) { bestv[i] = d; besti[i] = kt + tx*8 + j; }
            }
        }
    }

    // Cross-thread merge per row (first-index tie-break like argmin)
    __syncthreads();
    float* rmin = sm;
    int*   ridx = (int*)(sm + RM);
    if (tid < RM) { rmin[tid] = 3.0e38f; ridx[tid] = 0x7fffffff; }
    __syncthreads();
    for (int t = 0; t < 16; t++) {
        if (tx == t) {
            #pragma unroll
            for (int i = 0; i < 8; i++) {
                int lr = ty*8 + i;
                if (bestv[i] < rmin[lr] ||
                    (bestv[i] == rmin[lr] && besti[i] < ridx[lr])) {
                    rmin[lr] = bestv[i]; ridx[lr] = besti[i];
                }
            }
        }
        __syncthreads();
    }
    if (tid < RM) g_idx[rowbase + tid] = ridx[tid];
}

// ---------------------------------------------------------------------------
// Gather + BCHW output + SSE partials + histogram + idx output.
// Block per (b,h) strip, 256 threads.
__global__ void k_output(const float* __restrict__ emb, float* __restrict__ dout) {
    __shared__ float se[CDIM*(WW+1)];   // se[c*33 + w]
    __shared__ float sz[CDIM*(WW+1)];
    __shared__ int   sidx[WW];
    __shared__ float sred[8];
    int bh = blockIdx.x;
    int b = bh >> 5, h = bh & 31;
    int nbase = bh * WW;
    int tid = threadIdx.x;   // 256

    if (tid < WW) {
        int id = g_idx[nbase + tid];
        sidx[tid] = id;
        atomicAdd(&g_hist[id], 1u);
        dout[IDX_OFF + nbase + tid] = (float)id;
    }
    __syncthreads();

    for (int e = tid; e < WW*CDIM; e += 256) {
        int w = e >> 7, c = e & 127;     // c consecutive across lanes -> coalesced
        se[c*(WW+1) + w] = emb[(size_t)sidx[w]*CDIM + c];
        sz[c*(WW+1) + w] = g_z[(size_t)(nbase+w)*CDIM + c];
    }
    __syncthreads();

    float lsse = 0.f;
    for (int e = tid; e < CDIM*WW; e += 256) {
        int c = e >> 5, w = e & 31;      // w consecutive across lanes
        float q  = se[c*(WW+1) + w];
        float zz = sz[c*(WW+1) + w];
        float df = q - zz;
        lsse += df*df;
        dout[OUT_OFF + (((size_t)(b*CDIM + c))*HH + h)*WW + w] = q;
    }
    #pragma unroll
    for (int o = 16; o > 0; o >>= 1) lsse += __shfl_xor_sync(0xffffffffu, lsse, o);
    if ((tid & 31) == 0) sred[tid >> 5] = lsse;
    __syncthreads();
    if (tid == 0) {
        float s = 0.f;
        #pragma unroll
        for (int i = 0; i < 8; i++) s += sred[i];
        g_part[bh] = s;
    }
}

// ---------------------------------------------------------------------------
// Final scalars: loss and perplexity
__global__ void k_final(float* __restrict__ dout) {
    __shared__ double sr[256];
    int tid = threadIdx.x;
    double s = 0.0;
    for (int i = tid; i < 1024; i += 256) s += (double)g_part[i];
    sr[tid] = s; __syncthreads();
    for (int o = 128; o > 0; o >>= 1) {
        if (tid < o) sr[tid] += sr[tid + o];
        __syncthreads();
    }
    if (tid == 0) {
        double mse = sr[0] / (double)(NROWS*CDIM);
        dout[0] = (float)(1.25 * mse);   // q_latent + 0.25 * e_latent (numerically equal)
    }
    __syncthreads();
    double hs = 0.0;
    for (int k = tid; k < KCODES; k += 256) {
        double p = (double)g_hist[k] / (double)NROWS;
        hs += p * log(p + 1e-10);
    }
    sr[tid] = hs; __syncthreads();
    for (int o = 128; o > 0; o >>= 1) {
        if (tid < o) sr[tid] += sr[tid + o];
        __syncthreads();
    }
    if (tid == 0) dout[PERP_OFF] = (float)exp(-sr[0]);
}

// ---------------------------------------------------------------------------
extern "C" void kernel_launch(void* const* d_in, const int* in_sizes, int n_in,
                              void* d_out, int out_size) {
    const float* x   = (const float*)d_in[0];
    const float* Wl  = (const float*)d_in[1];
    const float* bl  = (const float*)d_in[2];
    const float* emb = (const float*)d_in[3];
    float* dout = (float*)d_out;

    cudaFuncSetAttribute(k_argmin, cudaFuncAttributeMaxDynamicSharedMemorySize, SMEM_ARGMIN);

    k_prep<<<96, 256>>>(Wl);
    k_esq<<<(KCODES*32)/256, 256>>>(emb);
    k_linear<<<BB*HH, 128>>>(x, bl);
    k_zsq<<<(NROWS*32)/256, 256>>>();
    k_argmin<<<NROWS/RM, 256, SMEM_ARGMIN>>>(emb);
    k_output<<<BB*HH, 256>>>(emb, dout);
    k_final<<<1, 256>>>(dout);
}

// round 2
// speedup vs baseline: 2.4683x; 2.4683x over previous
#include <cuda_runtime.h>
#include <math.h>

// Problem constants
#define NROWS 32768   // B*H*W
#define CDIM  128
#define KCODES 8192
#define BB 32
#define HH 32
#define WW 32

// Output buffer layout: [loss(1)] [out(B*C*H*W)] [perplexity(1)] [idx(NROWS)]
#define OUT_OFF  1
#define PERP_OFF (1 + NROWS*CDIM)
#define IDX_OFF  (PERP_OFF + 1)

// Scratch (static __device__ — no allocations allowed)
__device__ float g_z[NROWS*CDIM];      // projected inputs [N,C]
__device__ float g_zsq[NROWS];         // row squared norms of z
__device__ float g_esq[KCODES];        // row squared norms of emb
__device__ float g_wt[CDIM*CDIM];      // W_lin transposed: g_wt[c*C + j] = W[j,c]
__device__ int   g_idx[NROWS];         // argmin indices
__device__ float g_part[1024];         // per-block SSE partials
__device__ unsigned int g_hist[KCODES];// code usage histogram

// ---------------------------------------------------------------------------
// Prep: transpose W into g_wt, zero histogram
__global__ void k_prep(const float* __restrict__ Wl) {
    int i = blockIdx.x * 256 + threadIdx.x;
    if (i < CDIM*CDIM) {
        int j = i / CDIM, c = i % CDIM;
        g_wt[c*CDIM + j] = Wl[i];
    }
    int h = i - CDIM*CDIM;
    if (h >= 0 && h < KCODES) g_hist[h] = 0u;
}

// Row squared norms of emb: warp per row
__global__ void k_esq(const float* __restrict__ emb) {
    int warp = (blockIdx.x * blockDim.x + threadIdx.x) >> 5;
    int lane = threadIdx.x & 31;
    if (warp >= KCODES) return;
    const float* p = emb + (size_t)warp * CDIM;
    float s = 0.f;
    #pragma unroll
    for (int c = lane; c < CDIM; c += 32) { float v = p[c]; s += v*v; }
    #pragma unroll
    for (int o = 16; o > 0; o >>= 1) s += __shfl_xor_sync(0xffffffffu, s, o);
    if (lane == 0) g_esq[warp] = s;
}

// Row squared norms of z: warp per row
__global__ void k_zsq() {
    int warp = (blockIdx.x * blockDim.x + threadIdx.x) >> 5;
    int lane = threadIdx.x & 31;
    if (warp >= NROWS) return;
    const float* p = g_z + (size_t)warp * CDIM;
    float s = 0.f;
    #pragma unroll
    for (int c = lane; c < CDIM; c += 32) { float v = p[c]; s += v*v; }
    #pragma unroll
    for (int o = 16; o > 0; o >>= 1) s += __shfl_xor_sync(0xffffffffu, s, o);
    if (lane == 0) g_zsq[warp] = s;
}

// ---------------------------------------------------------------------------
// Linear projection: z[n,j] = sum_c x[b,c,h,w] * W[j,c] + b[j]
// Block per (b,h) strip (32 rows), 128 threads (one per output channel j).
__global__ void k_linear(const float* __restrict__ x, const float* __restrict__ bl) {
    __shared__ float xs[CDIM*WW];   // xs[c*32 + w]
    int bh = blockIdx.x;
    int b = bh >> 5, h = bh & 31;
    int tid = threadIdx.x;          // 128
    int w = tid & 31, cg = tid >> 5;
    const float* xp = x + ((size_t)(b*CDIM) * HH + h) * WW;  // x[b,0,h,0]
    #pragma unroll
    for (int cc = 0; cc < 32; cc++) {
        int c = cg*32 + cc;
        xs[c*WW + w] = xp[(size_t)c * (HH*WW) + w];
    }
    __syncthreads();

    int j = tid;
    float bj = bl[j];
    float acc[WW];
    #pragma unroll
    for (int ww = 0; ww < WW; ww++) acc[ww] = bj;

    #pragma unroll 4
    for (int c = 0; c < CDIM; c++) {
        float wv = g_wt[c*CDIM + j];
        #pragma unroll
        for (int w4 = 0; w4 < WW/4; w4++) {
            float4 xv = *(const float4*)&xs[c*WW + w4*4];
            acc[w4*4+0] += xv.x * wv;
            acc[w4*4+1] += xv.y * wv;
            acc[w4*4+2] += xv.z * wv;
            acc[w4*4+3] += xv.w * wv;
        }
    }
    int nbase = bh * WW;
    #pragma unroll
    for (int ww = 0; ww < WW; ww++)
        g_z[(size_t)(nbase+ww)*CDIM + j] = acc[ww];
}

// ---------------------------------------------------------------------------
// Fused distance + argmin. Block: 128 rows x (loop over K in 128-code tiles).
// 256 threads (16x16), 8x8 micro-tile per thread, packed f32x2 FMA.
// B operand stored channel-pair-major with padded stride; codes owned
// interleaved (code = jj*16 + tx) -> conflict-free LDS.
#define RM 128
#define KN 128
#define ESTRIDE 258   // floats per channel-pair row (2*128 + 2 pad)
#define SMEM_ARGMIN ((RM*CDIM + 64*ESTRIDE + KN) * 4)

__global__ void __launch_bounds__(256, 1) k_argmin(const float* __restrict__ emb) {
    extern __shared__ float sm[];
    float* zs  = sm;                    // RM*CDIM
    float* es2 = sm + RM*CDIM;          // 64*ESTRIDE : es2[c2*ESTRIDE + 2*j + {0,1}]
    float* ssq = es2 + 64*ESTRIDE;      // KN

    int tid = threadIdx.x;
    int tx = tid & 15, ty = tid >> 4;
    int rowbase = blockIdx.x * RM;

    // Load z tile (resident for whole K loop), row-major
    {
        const float4* src = (const float4*)(g_z + (size_t)rowbase * CDIM);
        float4* dst = (float4*)zs;
        for (int i = tid; i < RM*CDIM/4; i += 256) dst[i] = src[i];
    }
    float zsqr[8];
    #pragma unroll
    for (int i = 0; i < 8; i++) zsqr[i] = g_zsq[rowbase + ty*8 + i];

    float bestv[8]; int besti[8];
    #pragma unroll
    for (int i = 0; i < 8; i++) { bestv[i] = 3.0e38f; besti[i] = 0; }

    const float* zp = zs + (ty*8) * CDIM;

    for (int kt = 0; kt < KCODES; kt += KN) {
        __syncthreads();   // previous tile fully consumed
        // Load codebook tile, transposed into channel-pair-major layout.
        // i = j*64 + c2 : lane-varying c2 -> coalesced gmem float2 reads,
        // STS word = c2*258 + 2j -> banks (2*c2 + 2j)%32 -> 2-way only.
        {
            const float2* esrc = (const float2*)(emb + (size_t)kt * CDIM);
            for (int i = tid; i < KN*64; i += 256) {
                int j = i >> 6, c2 = i & 63;
                float2 v = esrc[i];
                *(float2*)&es2[c2*ESTRIDE + 2*j] = v;
            }
            if (tid < KN) ssq[tid] = g_esq[kt + tid];
        }
        __syncthreads();

        float esqr[8];
        #pragma unroll
        for (int jj = 0; jj < 8; jj++) esqr[jj] = ssq[jj*16 + tx];

        unsigned long long acc[8][8];
        #pragma unroll
        for (int i = 0; i < 8; i++)
            #pragma unroll
            for (int j = 0; j < 8; j++) acc[i][j] = 0ull;

        #pragma unroll 4
        for (int cc = 0; cc < 64; cc++) {
            unsigned long long af[8], bf[8];
            // af: broadcast across tx (2 distinct addrs/warp) -> conflict-free
            #pragma unroll
            for (int i = 0; i < 8; i++)
                af[i] = *(const unsigned long long*)(zp + i*CDIM + 2*cc);
            // bf: word = cc*258 + 32*jj + 2*tx -> 16 distinct bank-pairs -> conflict-free
            #pragma unroll
            for (int jj = 0; jj < 8; jj++)
                bf[jj] = *(const unsigned long long*)(es2 + cc*ESTRIDE + 32*jj + 2*tx);
            #pragma unroll
            for (int i = 0; i < 8; i++)
                #pragma unroll
                for (int jj = 0; jj < 8; jj++)
                    asm("fma.rn.f32x2 %0, %1, %2, %0;"
                        : "+l"(acc[i][jj]) : "l"(af[i]), "l"(bf[jj]));
        }

        // Epilogue: d = (zsq + esq) - 2*dot, rounding order matching reference.
        // Per-thread index stream (kt, jj ascending) is strictly increasing,
        // so strict '<' keeps the first (lowest) index on ties.
        #pragma unroll
        for (int i = 0; i < 8; i++) {
            #pragma unroll
            for (int jj = 0; jj < 8; jj++) {
                float lo = __uint_as_float((unsigned int)(acc[i][jj] & 0xffffffffull));
                float hi = __uint_as_float((unsigned int)(acc[i][jj] >> 32));
                float dot = __fadd_rn(lo, hi);
                float se  = __fadd_rn(zsqr[i], esqr[jj]);
                float d   = __fsub_rn(se, __fmul_rn(2.0f, dot));
                if (d < bestv[i]) { bestv[i] = d; besti[i] = kt + jj*16 + tx; }
            }
        }
    }

    // Cross-thread merge per row (first-index tie-break like argmin)
    __syncthreads();
    float* rmin = sm;
    int*   ridx = (int*)(sm + RM);
    if (tid < RM) { rmin[tid] = 3.0e38f; ridx[tid] = 0x7fffffff; }
    __syncthreads();
    for (int t = 0; t < 16; t++) {
        if (tx == t) {
            #pragma unroll
            for (int i = 0; i < 8; i++) {
                int lr = ty*8 + i;
                if (bestv[i] < rmin[lr] ||
                    (bestv[i] == rmin[lr] && besti[i] < ridx[lr])) {
                    rmin[lr] = bestv[i]; ridx[lr] = besti[i];
                }
            }
        }
        __syncthreads();
    }
    if (tid < RM) g_idx[rowbase + tid] = ridx[tid];
}

// ---------------------------------------------------------------------------
// Gather + BCHW output + SSE partials + histogram + idx output.
// Block per (b,h) strip, 256 threads.
__global__ void k_output(const float* __restrict__ emb, float* __restrict__ dout) {
    __shared__ float se[CDIM*(WW+1)];   // se[c*33 + w]
    __shared__ float sz[CDIM*(WW+1)];
    __shared__ int   sidx[WW];
    __shared__ float sred[8];
    int bh = blockIdx.x;
    int b = bh >> 5, h = bh & 31;
    int nbase = bh * WW;
    int tid = threadIdx.x;   // 256

    if (tid < WW) {
        int id = g_idx[nbase + tid];
        sidx[tid] = id;
        atomicAdd(&g_hist[id], 1u);
        dout[IDX_OFF + nbase + tid] = (float)id;
    }
    __syncthreads();

    for (int e = tid; e < WW*CDIM; e += 256) {
        int w = e >> 7, c = e & 127;     // c consecutive across lanes -> coalesced
        se[c*(WW+1) + w] = emb[(size_t)sidx[w]*CDIM + c];
        sz[c*(WW+1) + w] = g_z[(size_t)(nbase+w)*CDIM + c];
    }
    __syncthreads();

    float lsse = 0.f;
    for (int e = tid; e < CDIM*WW; e += 256) {
        int c = e >> 5, w = e & 31;      // w consecutive across lanes
        float q  = se[c*(WW+1) + w];
        float zz = sz[c*(WW+1) + w];
        float df = q - zz;
        lsse += df*df;
        dout[OUT_OFF + (((size_t)(b*CDIM + c))*HH + h)*WW + w] = q;
    }
    #pragma unroll
    for (int o = 16; o > 0; o >>= 1) lsse += __shfl_xor_sync(0xffffffffu, lsse, o);
    if ((tid & 31) == 0) sred[tid >> 5] = lsse;
    __syncthreads();
    if (tid == 0) {
        float s = 0.f;
        #pragma unroll
        for (int i = 0; i < 8; i++) s += sred[i];
        g_part[bh] = s;
    }
}

// ---------------------------------------------------------------------------
// Final scalars: loss and perplexity
__global__ void k_final(float* __restrict__ dout) {
    __shared__ double sr[256];
    int tid = threadIdx.x;
    double s = 0.0;
    for (int i = tid; i < 1024; i += 256) s += (double)g_part[i];
    sr[tid] = s; __syncthreads();
    for (int o = 128; o > 0; o >>= 1) {
        if (tid < o) sr[tid] += sr[tid + o];
        __syncthreads();
    }
    if (tid == 0) {
        double mse = sr[0] / (double)(NROWS*CDIM);
        dout[0] = (float)(1.25 * mse);   // q_latent + 0.25 * e_latent (numerically equal)
    }
    __syncthreads();
    double hs = 0.0;
    for (int k = tid; k < KCODES; k += 256) {
        double p = (double)g_hist[k] / (double)NROWS;
        hs += p * log(p + 1e-10);
    }
    sr[tid] = hs; __syncthreads();
    for (int o = 128; o > 0; o >>= 1) {
        if (tid < o) sr[tid] += sr[tid + o];
        __syncthreads();
    }
    if (tid == 0) dout[PERP_OFF] = (float)exp(-sr[0]);
}

// ---------------------------------------------------------------------------
extern "C" void kernel_launch(void* const* d_in, const int* in_sizes, int n_in,
                              void* d_out, int out_size) {
    const float* x   = (const float*)d_in[0];
    const float* Wl  = (const float*)d_in[1];
    const float* bl  = (const float*)d_in[2];
    const float* emb = (const float*)d_in[3];
    float* dout = (float*)d_out;

    cudaFuncSetAttribute(k_argmin, cudaFuncAttributeMaxDynamicSharedMemorySize, SMEM_ARGMIN);

    k_prep<<<96, 256>>>(Wl);
    k_esq<<<(KCODES*32)/256, 256>>>(emb);
    k_linear<<<BB*HH, 128>>>(x, bl);
    k_zsq<<<(NROWS*32)/256, 256>>>();
    k_argmin<<<NROWS/RM, 256, SMEM_ARGMIN>>>(emb);
    k_output<<<BB*HH, 256>>>(emb, dout);
    k_final<<<1, 256>>>(dout);
}